// round 4
// baseline (speedup 1.0000x reference)
#include <cuda_runtime.h>

typedef unsigned long long u64;

#define B_  64
#define P_  196
#define T_  20
#define D_  512
#define C_  256
#define V_  30000

// ---------------- static scratch ----------------
__device__ float g_featsT[B_ * P_ * C_];        // [12544, 256]
__device__ float g_enc_att[B_ * P_ * D_];       // [12544, 512]
__device__ float g_embsG[1280 * 512];           // row r = b*20+t
__device__ float g_pre_gates[1280 * 2048];      // emb part of gates (+biases)
__device__ float g_WtihE[512 * 2048];           // W_ih[:, 0:512]^T
__device__ float g_Wbig[768 * 2048];            // [0:256) = W_ih[:,512:768]^T ; [256:768) = W_hh^T
__device__ float g_bias_g[2048];                // b_ih + b_hh
__device__ float g_decP[8 * 64 * 512];          // k-split partials for dec_att
__device__ float g_gateP[4 * 64 * 2048];        // k-split partials for gates
__device__ float g_X[64 * 768];                 // [ctx(256) | h(512)] per batch
__device__ float g_c[64 * 512];                 // LSTM cell state
__device__ float g_Hall[1280 * 512];            // all h_t, row r = b*20+t
__device__ int   g_is64;

// ---------------- f32x2 helpers ----------------
__device__ __forceinline__ u64 pack_dup(float x) {
    u64 r; unsigned u = __float_as_uint(x);
    asm("mov.b64 %0, {%1, %1};" : "=l"(r) : "r"(u));
    return r;
}
__device__ __forceinline__ void ffma2(u64& c, u64 a, u64 b) {
    asm("fma.rn.f32x2 %0, %1, %2, %0;" : "+l"(c) : "l"(a), "l"(b));
}
__device__ __forceinline__ float2 unpack2(u64 v) {
    unsigned lo, hi;
    asm("mov.b64 {%0, %1}, %2;" : "=r"(lo), "=r"(hi) : "l"(v));
    float2 f; f.x = __uint_as_float(lo); f.y = __uint_as_float(hi);
    return f;
}
union F4U { float4 v; u64 u[2]; };

// ---------------- captions dtype detection ----------------
__global__ void detect_dtype(const void* __restrict__ cap) {
    __shared__ int ok;
    if (threadIdx.x == 0) ok = 1;
    __syncthreads();
    const long long* c = (const long long*)cap;
    for (int i = threadIdx.x; i < 640; i += 256) {   // 640*8 = 5120B: in-bounds for both layouts
        long long v = c[i];
        if (v < 0 || v >= V_) atomicAnd(&ok, 0);
    }
    __syncthreads();
    if (threadIdx.x == 0) g_is64 = ok;
}

// ---------------- embedding gather ----------------
__global__ void gather_emb(const void* __restrict__ cap, const float* __restrict__ emb) {
    int r = blockIdx.x;
    long long idx = g_is64 ? ((const long long*)cap)[r]
                           : (long long)((const int*)cap)[r];
    const float4* src = (const float4*)(emb + (size_t)idx * 512);
    float4* dst = (float4*)(g_embsG + (size_t)r * 512);
    dst[threadIdx.x] = src[threadIdx.x];   // 128 * float4 = 512 floats
}

// ---------------- feats transpose: [B,C,P] -> [B*P, C] ----------------
__global__ void feats_transpose(const float* __restrict__ encF) {
    __shared__ float tile[32][33];
    int p0 = blockIdx.x * 32, c0 = blockIdx.y * 32, b = blockIdx.z;
    int tx = threadIdx.x, ty = threadIdx.y;
#pragma unroll
    for (int i = 0; i < 32; i += 8) {
        int c = c0 + ty + i, p = p0 + tx;
        tile[ty + i][tx] = (p < P_) ? encF[((size_t)b * C_ + c) * P_ + p] : 0.f;
    }
    __syncthreads();
#pragma unroll
    for (int i = 0; i < 32; i += 8) {
        int p = p0 + ty + i, c = c0 + tx;
        if (p < P_) g_featsT[((size_t)b * P_ + p) * C_ + c] = tile[tx][ty + i];
    }
}

// ---------------- weight transpose: dst[k][j] = src[j][koff+k] ----------------
__global__ void transposeW(const float* __restrict__ src, float* __restrict__ dst,
                           int J, int ldsrc, int koff) {
    __shared__ float tile[32][33];
    int j0 = blockIdx.x * 32, k0 = blockIdx.y * 32;
    int tx = threadIdx.x, ty = threadIdx.y;
#pragma unroll
    for (int i = 0; i < 32; i += 8)
        tile[ty + i][tx] = src[(size_t)(j0 + ty + i) * ldsrc + koff + k0 + tx];
    __syncthreads();
#pragma unroll
    for (int i = 0; i < 32; i += 8)
        dst[(size_t)(k0 + ty + i) * J + j0 + tx] = tile[tx][ty + i];
}

// ---------------- init ----------------
__global__ void init_state() {
    int i = blockIdx.x * blockDim.x + threadIdx.x;
    if (i < 64 * 768) g_X[i] = 0.f;
    if (i < 64 * 512) g_c[i] = 0.f;
    if (i < 8 * 64 * 512) g_decP[i] = 0.f;
}
__global__ void make_gate_bias(const float* __restrict__ b_ih, const float* __restrict__ b_hh) {
    int i = blockIdx.x * blockDim.x + threadIdx.x;
    if (i < 2048) g_bias_g[i] = b_ih[i] + b_hh[i];
}

// ---------------- 128x128x8 SGEMM, f32x2 inner, prefetch double-buffer ----------------
__global__ __launch_bounds__(256, 2)
void sgemm128(const float* __restrict__ A, const float* __restrict__ B,
              const float* __restrict__ bias, float* __restrict__ C,
              int M, int N, int K) {
    __shared__ float As[8][128];
    __shared__ float Bs[8][128];
    const int tid = threadIdx.x;
    const int row0 = blockIdx.y * 128, col0 = blockIdx.x * 128;
    const int tr = tid >> 4, tc = tid & 15;
    const int aRow = tid >> 1, aCol = (tid & 1) << 2;
    const int bRow = tid >> 5, bCol = (tid & 31) << 2;

    u64 acc[8][4];
#pragma unroll
    for (int i = 0; i < 8; i++)
#pragma unroll
        for (int j = 0; j < 4; j++) acc[i][j] = 0ULL;

    const bool mOK = (row0 + aRow) < M;
    const int bc = col0 + bCol;

    float4 av = make_float4(0, 0, 0, 0), bv = make_float4(0, 0, 0, 0);
    if (mOK) av = *reinterpret_cast<const float4*>(A + (size_t)(row0 + aRow) * K + aCol);
    {
        const float* Bp = B + (size_t)bRow * N + bc;
        if (bc + 3 < N) bv = *reinterpret_cast<const float4*>(Bp);
        else if (bc < N) { bv.x = Bp[0]; if (bc + 1 < N) bv.y = Bp[1]; if (bc + 2 < N) bv.z = Bp[2]; }
    }

    for (int k0 = 0; k0 < K; k0 += 8) {
        As[aCol + 0][aRow] = av.x; As[aCol + 1][aRow] = av.y;
        As[aCol + 2][aRow] = av.z; As[aCol + 3][aRow] = av.w;
        *reinterpret_cast<float4*>(&Bs[bRow][bCol]) = bv;
        __syncthreads();

        if (k0 + 8 < K) {
            av = make_float4(0, 0, 0, 0); bv = make_float4(0, 0, 0, 0);
            if (mOK) av = *reinterpret_cast<const float4*>(A + (size_t)(row0 + aRow) * K + k0 + 8 + aCol);
            const float* Bp = B + (size_t)(k0 + 8 + bRow) * N + bc;
            if (bc + 3 < N) bv = *reinterpret_cast<const float4*>(Bp);
            else if (bc < N) { bv.x = Bp[0]; if (bc + 1 < N) bv.y = Bp[1]; if (bc + 2 < N) bv.z = Bp[2]; }
        }

#pragma unroll
        for (int kk = 0; kk < 8; kk++) {
            float4 a0 = *reinterpret_cast<const float4*>(&As[kk][tr * 8]);
            float4 a1 = *reinterpret_cast<const float4*>(&As[kk][tr * 8 + 4]);
            F4U b0, b1;
            b0.v = *reinterpret_cast<const float4*>(&Bs[kk][tc * 8]);
            b1.v = *reinterpret_cast<const float4*>(&Bs[kk][tc * 8 + 4]);
            float ar[8] = {a0.x, a0.y, a0.z, a0.w, a1.x, a1.y, a1.z, a1.w};
            u64 bb[4] = {b0.u[0], b0.u[1], b1.u[0], b1.u[1]};
#pragma unroll
            for (int i = 0; i < 8; i++) {
                u64 a2 = pack_dup(ar[i]);
#pragma unroll
                for (int j = 0; j < 4; j++) ffma2(acc[i][j], a2, bb[j]);
            }
        }
        __syncthreads();
    }

#pragma unroll
    for (int i = 0; i < 8; i++) {
        int r = row0 + tr * 8 + i;
        if (r >= M) continue;
#pragma unroll
        for (int j = 0; j < 4; j++) {
            float2 v = unpack2(acc[i][j]);
            int c = col0 + tc * 8 + j * 2;
            if (c < N)     C[(size_t)r * N + c]     = v.x + bias[c];
            if (c + 1 < N) C[(size_t)r * N + c + 1] = v.y + bias[c + 1];
        }
    }
}

// ---------------- M=64 k-split GEMM: partial[ks][64][N-tile] = X[:, ks-slice] @ W[ks-slice, :] ----------------
__global__ __launch_bounds__(256, 2)
void gemm64_ksplit(const float* __restrict__ X, int ldx,
                   const float* __restrict__ W,
                   float* __restrict__ partial, int N, int Kper) {
    __shared__ float Xs[64][68];
    __shared__ float Ws[64][64];
    const int nc = blockIdx.x, ks = blockIdx.y;
    const int col0 = nc * 64;
    const int kbase = ks * Kper;
    const int tid = threadIdx.x;
    const int tr = tid >> 4, tc = tid & 15;

    u64 acc[4][2];
#pragma unroll
    for (int i = 0; i < 4; i++) { acc[i][0] = 0ULL; acc[i][1] = 0ULL; }

    for (int kt = 0; kt < Kper; kt += 64) {
#pragma unroll
        for (int i = 0; i < 4; i++) {
            int g = tid + 256 * i;
            int r = g >> 4, c4 = (g & 15) << 2;
            float4 xv = *reinterpret_cast<const float4*>(X + (size_t)r * ldx + kbase + kt + c4);
            Xs[r][c4 + 0] = xv.x; Xs[r][c4 + 1] = xv.y; Xs[r][c4 + 2] = xv.z; Xs[r][c4 + 3] = xv.w;
            float4 wv = *reinterpret_cast<const float4*>(W + (size_t)(kbase + kt + r) * N + col0 + c4);
            *reinterpret_cast<float4*>(&Ws[r][c4]) = wv;
        }
        __syncthreads();
#pragma unroll 8
        for (int kk = 0; kk < 64; kk++) {
            u64 d0 = pack_dup(Xs[tr * 4 + 0][kk]);
            u64 d1 = pack_dup(Xs[tr * 4 + 1][kk]);
            u64 d2 = pack_dup(Xs[tr * 4 + 2][kk]);
            u64 d3 = pack_dup(Xs[tr * 4 + 3][kk]);
            const u64* wp = reinterpret_cast<const u64*>(&Ws[kk][tc * 4]);
            u64 b0 = wp[0], b1 = wp[1];
            ffma2(acc[0][0], d0, b0); ffma2(acc[0][1], d0, b1);
            ffma2(acc[1][0], d1, b0); ffma2(acc[1][1], d1, b1);
            ffma2(acc[2][0], d2, b0); ffma2(acc[2][1], d2, b1);
            ffma2(acc[3][0], d3, b0); ffma2(acc[3][1], d3, b1);
        }
        __syncthreads();
    }
#pragma unroll
    for (int i = 0; i < 4; i++) {
        int m = tr * 4 + i;
#pragma unroll
        for (int j = 0; j < 2; j++) {
            float2 v = unpack2(acc[i][j]);
            int c = col0 + tc * 4 + j * 2;
            partial[((size_t)ks * 64 + m) * N + c]     = v.x;
            partial[((size_t)ks * 64 + m) * N + c + 1] = v.y;
        }
    }
}

// ---------------- fused attention: dec-partial reduce + scores + softmax + context ----------------
__global__ __launch_bounds__(256)
void attention_kernel(const float* __restrict__ b_dec, const float* __restrict__ W_full,
                      const float* __restrict__ b_full) {
    const int b = blockIdx.x;
    const int tid = threadIdx.x;
    const int warp = tid >> 5, lane = tid & 31;
    __shared__ float dec_s[512];
    __shared__ float wf_s[512];
    __shared__ float att_s[256];
    __shared__ float red_s[8];

    for (int a = tid; a < 512; a += 256) {
        float s = b_dec[a];
#pragma unroll
        for (int ks = 0; ks < 8; ks++) s += g_decP[((size_t)ks * 64 + b) * 512 + a];
        dec_s[a] = s;
        wf_s[a] = W_full[a];
    }
    __syncthreads();

    // scores: one p per warp per iteration
    for (int p = warp; p < P_; p += 8) {
        const float* ea = g_enc_att + ((size_t)b * P_ + p) * 512;
        float partial = 0.f;
#pragma unroll 4
        for (int a = lane; a < 512; a += 32)
            partial += fmaxf(ea[a] + dec_s[a], 0.f) * wf_s[a];
#pragma unroll
        for (int o = 16; o > 0; o >>= 1) partial += __shfl_xor_sync(0xffffffffu, partial, o);
        if (lane == 0) att_s[p] = partial + b_full[0];
    }
    __syncthreads();

    // softmax over 196
    float v = (tid < P_) ? att_s[tid] : -3.4e38f;
    float m = v;
#pragma unroll
    for (int o = 16; o > 0; o >>= 1) m = fmaxf(m, __shfl_xor_sync(0xffffffffu, m, o));
    if (lane == 0) red_s[warp] = m;
    __syncthreads();
    if (warp == 0) {
        float mm = red_s[lane & 7];
#pragma unroll
        for (int o = 4; o > 0; o >>= 1) mm = fmaxf(mm, __shfl_xor_sync(0xffffffffu, mm, o));
        if (lane == 0) red_s[0] = mm;
    }
    __syncthreads();
    float gmax = red_s[0];
    float e = (tid < P_) ? expf(v - gmax) : 0.f;
    float s = e;
#pragma unroll
    for (int o = 16; o > 0; o >>= 1) s += __shfl_xor_sync(0xffffffffu, s, o);
    __syncthreads();
    if (lane == 0) red_s[warp] = s;
    __syncthreads();
    if (warp == 0) {
        float ss = red_s[lane & 7];
#pragma unroll
        for (int o = 4; o > 0; o >>= 1) ss += __shfl_xor_sync(0xffffffffu, ss, o);
        if (lane == 0) red_s[0] = ss;
    }
    __syncthreads();
    float inv = 1.f / red_s[0];
    if (tid < P_) att_s[tid] = e * inv;
    __syncthreads();

    // context[c] = sum_p featsT[b,p,c] * alpha[p]   (c = tid, 256 exactly)
    {
        const float* fb = g_featsT + (size_t)b * P_ * C_ + tid;
        float ctx = 0.f;
#pragma unroll 4
        for (int p = 0; p < P_; p++)
            ctx += fb[(size_t)p * C_] * att_s[p];
        g_X[(size_t)b * 768 + tid] = ctx;
    }
}

// ---------------- LSTM pointwise finalize ----------------
__global__ __launch_bounds__(512)
void lstm_finalize(int t) {
    const int b = blockIdx.x, d = threadIdx.x;
    const size_t pr = ((size_t)b * T_ + t) * 2048;

    float gi = g_pre_gates[pr + d];
    float gf = g_pre_gates[pr + 512 + d];
    float gg = g_pre_gates[pr + 1024 + d];
    float go = g_pre_gates[pr + 1536 + d];
#pragma unroll
    for (int ks = 0; ks < 4; ks++) {
        const float* gp = g_gateP + ((size_t)ks * 64 + b) * 2048;
        gi += gp[d]; gf += gp[512 + d]; gg += gp[1024 + d]; go += gp[1536 + d];
    }
    float si = 1.f / (1.f + expf(-gi));
    float sf = 1.f / (1.f + expf(-gf));
    float so = 1.f / (1.f + expf(-go));
    float tg = tanhf(gg);
    float cn = sf * g_c[(size_t)b * 512 + d] + si * tg;
    float hn = so * tanhf(cn);
    g_c[(size_t)b * 512 + d] = cn;
    g_X[(size_t)b * 768 + 256 + d] = hn;
    g_Hall[((size_t)b * T_ + t) * 512 + d] = hn;
}

// ---------------- launch ----------------
extern "C" void kernel_launch(void* const* d_in, const int* in_sizes, int n_in,
                              void* d_out, int out_size) {
    const float* encF   = (const float*)d_in[0];
    const void*  cap    = d_in[1];
    const float* W_enc  = (const float*)d_in[2];
    const float* b_enc  = (const float*)d_in[3];
    const float* W_dec  = (const float*)d_in[4];
    const float* b_dec  = (const float*)d_in[5];
    const float* W_full = (const float*)d_in[6];
    const float* b_full = (const float*)d_in[7];
    const float* emb    = (const float*)d_in[8];
    const float* W_ih   = (const float*)d_in[9];
    const float* b_ih   = (const float*)d_in[10];
    const float* W_hh   = (const float*)d_in[11];
    const float* b_hh   = (const float*)d_in[12];
    const float* W_fc   = (const float*)d_in[13];
    const float* b_fc   = (const float*)d_in[14];
    float* out = (float*)d_out;

    float *g_featsT_p, *g_enc_att_p, *g_embsG_p, *g_pre_p, *g_WtihE_p, *g_Wbig_p;
    float *g_bias_p, *g_X_p, *g_Hall_p;
    cudaGetSymbolAddress((void**)&g_featsT_p, g_featsT);
    cudaGetSymbolAddress((void**)&g_enc_att_p, g_enc_att);
    cudaGetSymbolAddress((void**)&g_embsG_p, g_embsG);
    cudaGetSymbolAddress((void**)&g_pre_p, g_pre_gates);
    cudaGetSymbolAddress((void**)&g_WtihE_p, g_WtihE);
    cudaGetSymbolAddress((void**)&g_Wbig_p, g_Wbig);
    cudaGetSymbolAddress((void**)&g_bias_p, g_bias_g);
    cudaGetSymbolAddress((void**)&g_X_p, g_X);
    cudaGetSymbolAddress((void**)&g_Hall_p, g_Hall);
    float *g_decP_p, *g_gateP_p;
    cudaGetSymbolAddress((void**)&g_decP_p, g_decP);
    cudaGetSymbolAddress((void**)&g_gateP_p, g_gateP);

    // ---- setup / hoisted work ----
    detect_dtype<<<1, 256>>>(cap);
    gather_emb<<<1280, 128>>>(cap, emb);
    feats_transpose<<<dim3(7, 8, 64), dim3(32, 8)>>>(encF);
    transposeW<<<dim3(64, 16), dim3(32, 8)>>>(W_ih, g_WtihE_p, 2048, 768, 0);   // emb cols
    transposeW<<<dim3(64, 8),  dim3(32, 8)>>>(W_ih, g_Wbig_p, 2048, 768, 512);  // ctx cols -> rows 0..255
    transposeW<<<dim3(64, 16), dim3(32, 8)>>>(W_hh, g_Wbig_p + (size_t)256 * 2048, 2048, 512, 0);
    init_state<<<1024, 256>>>();
    make_gate_bias<<<8, 256>>>(b_ih, b_hh);

    // enc_att = featsT @ W_enc + b_enc   [12544,256]@[256,512]
    sgemm128<<<dim3(4, 98), 256>>>(g_featsT_p, W_enc, b_enc, g_enc_att_p, 12544, 512, 256);
    // pre_gates = embsG @ W_ih[:, :512]^T + (b_ih + b_hh)   [1280,512]@[512,2048]
    sgemm128<<<dim3(16, 10), 256>>>(g_embsG_p, g_WtihE_p, g_bias_p, g_pre_p, 1280, 2048, 512);

    // ---- recurrence ----
    for (int t = 0; t < T_; t++) {
        attention_kernel<<<64, 256>>>(b_dec, W_full, b_full);
        gemm64_ksplit<<<dim3(32, 4), 256>>>(g_X_p, 768, g_Wbig_p, g_gateP_p, 2048, 192);
        lstm_finalize<<<64, 512>>>(t);
        gemm64_ksplit<<<dim3(8, 8), 256>>>(g_X_p + 256, 768, W_dec, g_decP_p, 512, 64);
    }

    // ---- deferred output projection: out = Hall @ W_fc + b_fc   [1280,512]@[512,30000]
    sgemm128<<<dim3(235, 10), 256>>>(g_Hall_p, W_fc, b_fc, out, 1280, 30000, 512);
}

// round 8
// speedup vs baseline: 1.2990x; 1.2990x over previous
#include <cuda_runtime.h>
#include <cuda_bf16.h>
#include <cstdint>

typedef unsigned long long u64;

#define B_  64
#define P_  196
#define T_  20
#define D_  512
#define C_  256
#define V_  30000

// fc HMMA config
#define FC_KP     1536            // K' = 3 * 512 (split-bf16 folded into K)
#define FC_NPAD   30208           // 236 * 128
#define FC_BM     128
#define FC_BN     128
#define FC_BK     64
#define FC_NCH    (FC_KP / FC_BK) // 24
#define FC_PITCH  144             // 72 bf16 per smem row (bytes)
#define FC_ATILE  (FC_BM * FC_PITCH)   // 18432
#define FC_STAGE  (2 * FC_ATILE)       // A + B = 36864
#define FC_SMEM   (2 * FC_STAGE)       // 73728

// ---------------- static scratch ----------------
__device__ float g_featsT[B_ * P_ * C_];
__device__ float g_enc_att[B_ * P_ * D_];
__device__ float g_embsG[1280 * 512];
__device__ float g_pre_gates[1280 * 2048];
__device__ float g_WtihE[512 * 2048];
__device__ float g_Wbig[768 * 2048];
__device__ float g_bias_g[2048];
__device__ float g_decP[8 * 64 * 512];
__device__ float g_gateP[4 * 64 * 2048];
__device__ float g_X[64 * 768];
__device__ float g_c[64 * 512];
__device__ float g_Hall[1280 * 512];
__device__ int   g_is64;
__device__ __nv_bfloat16 g_Ap[1280 * FC_KP];        // [hi | lo | hi] of Hall
__device__ __nv_bfloat16 g_Bp[FC_NPAD * FC_KP];     // [hi | hi | lo] of W_fc^T (padded rows)

// ---------------- f32x2 helpers ----------------
__device__ __forceinline__ u64 pack_dup(float x) {
    u64 r; unsigned u = __float_as_uint(x);
    asm("mov.b64 %0, {%1, %1};" : "=l"(r) : "r"(u));
    return r;
}
__device__ __forceinline__ void ffma2(u64& c, u64 a, u64 b) {
    asm("fma.rn.f32x2 %0, %1, %2, %0;" : "+l"(c) : "l"(a), "l"(b));
}
__device__ __forceinline__ float2 unpack2(u64 v) {
    unsigned lo, hi;
    asm("mov.b64 {%0, %1}, %2;" : "=r"(lo), "=r"(hi) : "l"(v));
    float2 f; f.x = __uint_as_float(lo); f.y = __uint_as_float(hi);
    return f;
}
union F4U { float4 v; u64 u[2]; };

// ---------------- baseline-PTX MMA helpers (sm_80+, legal on compute_103) ----------------
__device__ __forceinline__ uint32_t smem_u32(const void* p) {
    uint32_t a;
    asm("{ .reg .u64 t; cvta.to.shared.u64 t, %1; cvt.u32.u64 %0, t; }" : "=r"(a) : "l"(p));
    return a;
}
__device__ __forceinline__ void cp16(uint32_t s, const void* g) {
    asm volatile("cp.async.cg.shared.global [%0], [%1], 16;" :: "r"(s), "l"(g));
}
#define CP_COMMIT() asm volatile("cp.async.commit_group;" ::: "memory")
#define CP_WAIT1()  asm volatile("cp.async.wait_group 1;" ::: "memory")
#define CP_WAIT0()  asm volatile("cp.async.wait_group 0;" ::: "memory")

__device__ __forceinline__ void ldm4(uint32_t* r, uint32_t addr) {
    asm volatile("ldmatrix.sync.aligned.m8n8.x4.shared.b16 {%0,%1,%2,%3}, [%4];"
        : "=r"(r[0]), "=r"(r[1]), "=r"(r[2]), "=r"(r[3]) : "r"(addr));
}
__device__ __forceinline__ void mma16816(float* d, const uint32_t* a, uint32_t b0, uint32_t b1) {
    asm volatile("mma.sync.aligned.m16n8k16.row.col.f32.bf16.bf16.f32 "
        "{%0,%1,%2,%3}, {%4,%5,%6,%7}, {%8,%9}, {%0,%1,%2,%3};"
        : "+f"(d[0]), "+f"(d[1]), "+f"(d[2]), "+f"(d[3])
        : "r"(a[0]), "r"(a[1]), "r"(a[2]), "r"(a[3]), "r"(b0), "r"(b1));
}

// ---------------- captions dtype detection ----------------
__global__ void detect_dtype(const void* __restrict__ cap) {
    __shared__ int ok;
    if (threadIdx.x == 0) ok = 1;
    __syncthreads();
    const long long* c = (const long long*)cap;
    for (int i = threadIdx.x; i < 640; i += 256) {
        long long v = c[i];
        if (v < 0 || v >= V_) atomicAnd(&ok, 0);
    }
    __syncthreads();
    if (threadIdx.x == 0) g_is64 = ok;
}

// ---------------- embedding gather ----------------
__global__ void gather_emb(const void* __restrict__ cap, const float* __restrict__ emb) {
    int r = blockIdx.x;
    long long idx = g_is64 ? ((const long long*)cap)[r]
                           : (long long)((const int*)cap)[r];
    const float4* src = (const float4*)(emb + (size_t)idx * 512);
    float4* dst = (float4*)(g_embsG + (size_t)r * 512);
    dst[threadIdx.x] = src[threadIdx.x];
}

// ---------------- feats transpose: [B,C,P] -> [B*P, C] ----------------
__global__ void feats_transpose(const float* __restrict__ encF) {
    __shared__ float tile[32][33];
    int p0 = blockIdx.x * 32, c0 = blockIdx.y * 32, b = blockIdx.z;
    int tx = threadIdx.x, ty = threadIdx.y;
#pragma unroll
    for (int i = 0; i < 32; i += 8) {
        int c = c0 + ty + i, p = p0 + tx;
        tile[ty + i][tx] = (p < P_) ? encF[((size_t)b * C_ + c) * P_ + p] : 0.f;
    }
    __syncthreads();
#pragma unroll
    for (int i = 0; i < 32; i += 8) {
        int p = p0 + ty + i, c = c0 + tx;
        if (p < P_) g_featsT[((size_t)b * P_ + p) * C_ + c] = tile[tx][ty + i];
    }
}

// ---------------- weight transpose ----------------
__global__ void transposeW(const float* __restrict__ src, float* __restrict__ dst,
                           int J, int ldsrc, int koff) {
    __shared__ float tile[32][33];
    int j0 = blockIdx.x * 32, k0 = blockIdx.y * 32;
    int tx = threadIdx.x, ty = threadIdx.y;
#pragma unroll
    for (int i = 0; i < 32; i += 8)
        tile[ty + i][tx] = src[(size_t)(j0 + ty + i) * ldsrc + koff + k0 + tx];
    __syncthreads();
#pragma unroll
    for (int i = 0; i < 32; i += 8)
        dst[(size_t)(k0 + ty + i) * J + j0 + tx] = tile[tx][ty + i];
}

// ---------------- init ----------------
__global__ void init_state() {
    int i = blockIdx.x * blockDim.x + threadIdx.x;
    if (i < 64 * 768) g_X[i] = 0.f;
    if (i < 64 * 512) g_c[i] = 0.f;
    if (i < 8 * 64 * 512) g_decP[i] = 0.f;
}
__global__ void make_gate_bias(const float* __restrict__ b_ih, const float* __restrict__ b_hh) {
    int i = blockIdx.x * blockDim.x + threadIdx.x;
    if (i < 2048) g_bias_g[i] = b_ih[i] + b_hh[i];
}

// ---------------- build B' = split-bf16 of W_fc^T : [hi | hi | lo] along K' ----------------
__global__ void build_Bp(const float* __restrict__ Wfc) {
    __shared__ float t[32][33];
    int n0 = blockIdx.x * 32, k0 = blockIdx.y * 32;
    int tx = threadIdx.x, ty = threadIdx.y;
#pragma unroll
    for (int i = 0; i < 32; i += 8) {
        int n = n0 + tx;
        t[ty + i][tx] = (n < V_) ? Wfc[(size_t)(k0 + ty + i) * V_ + n] : 0.f;
    }
    __syncthreads();
#pragma unroll
    for (int i = 0; i < 32; i += 8) {
        int n = n0 + ty + i;
        if (n < V_) {
            float w = t[tx][ty + i];
            __nv_bfloat16 hi = __float2bfloat16(w);
            __nv_bfloat16 lo = __float2bfloat16(w - __bfloat162float(hi));
            size_t base = (size_t)n * FC_KP + k0 + tx;
            g_Bp[base]        = hi;
            g_Bp[base + 512]  = hi;
            g_Bp[base + 1024] = lo;
        }
    }
}

// ---------------- zero-pad B' rows 30000..30207 (avoid NaN garbage in MMA) ----------------
__global__ void pad_Bp() {
    int r = V_ + blockIdx.x;           // 208 rows
    __nv_bfloat16 z = __float2bfloat16(0.f);
    for (int k = threadIdx.x; k < FC_KP; k += 256)
        g_Bp[(size_t)r * FC_KP + k] = z;
}

// ---------------- build A' = split-bf16 of Hall : [hi | lo | hi] along K' ----------------
__global__ void build_Ap() {
    int r = blockIdx.x;
    for (int k = threadIdx.x; k < 512; k += 256) {
        float w = g_Hall[(size_t)r * 512 + k];
        __nv_bfloat16 hi = __float2bfloat16(w);
        __nv_bfloat16 lo = __float2bfloat16(w - __bfloat162float(hi));
        size_t base = (size_t)r * FC_KP + k;
        g_Ap[base]        = hi;
        g_Ap[base + 512]  = lo;
        g_Ap[base + 1024] = hi;
    }
}

// ---------------- fc GEMM via mma.sync bf16 (baseline PTX; works on compute_103) ----------------
// out[1280,30000] = A'[1280,1536] @ B'[30208,1536]^T + b_fc
__global__ __launch_bounds__(256, 2)
void fc_hmma(const __nv_bfloat16* __restrict__ Ap, const __nv_bfloat16* __restrict__ Bp,
             const float* __restrict__ bias, float* __restrict__ out) {
    extern __shared__ char smem[];
    const uint32_t sb = smem_u32(smem);
    const int tid = threadIdx.x, wid = tid >> 5, lane = tid & 31;
    const int warp_m = wid & 3, warp_n = wid >> 2;     // 4 x 2 warps
    const int row0 = blockIdx.y * FC_BM;
    const int col0 = blockIdx.x * FC_BN;

    const char* Ag = (const char*)(Ap + (size_t)row0 * FC_KP);
    const char* Bg = (const char*)(Bp + (size_t)col0 * FC_KP);
    const int KP2 = FC_KP * 2;

    // per-thread fill coordinates: 1024 16B-chunks per matrix, 4 per thread
    const int fr = tid >> 3;            // rows fr, fr+32, fr+64, fr+96
    const int fc16 = (tid & 7) * 16;    // byte offset within 128B row

    // stage fill (cp.async): stage s, chunk ch
    auto fill = [&](int s, int ch) {
        uint32_t sA = sb + s * FC_STAGE;
        uint32_t sB = sA + FC_ATILE;
        const char* Ac = Ag + ch * (FC_BK * 2);
        const char* Bc = Bg + ch * (FC_BK * 2);
#pragma unroll
        for (int i = 0; i < 4; i++) {
            int r = fr + i * 32;
            cp16(sA + r * FC_PITCH + fc16, Ac + (size_t)r * KP2 + fc16);
        }
#pragma unroll
        for (int i = 0; i < 4; i++) {
            int r = fr + i * 32;
            cp16(sB + r * FC_PITCH + fc16, Bc + (size_t)r * KP2 + fc16);
        }
        CP_COMMIT();
    };

    float d[2][8][4];
#pragma unroll
    for (int mi = 0; mi < 2; mi++)
#pragma unroll
        for (int j = 0; j < 8; j++)
#pragma unroll
            for (int q = 0; q < 4; q++) d[mi][j][q] = 0.f;

    // ldmatrix per-lane base addresses (row = l&15, col-half = l>>4)
    const uint32_t lmOff = (uint32_t)((lane & 15) * FC_PITCH + (lane >> 4) * 16);

    fill(0, 0);

    for (int ch = 0; ch < FC_NCH; ch++) {
        if (ch + 1 < FC_NCH) { fill((ch + 1) & 1, ch + 1); CP_WAIT1(); }
        else                 { CP_WAIT0(); }
        __syncthreads();

        const uint32_t sA = sb + (ch & 1) * FC_STAGE;
        const uint32_t sB = sA + FC_ATILE;
        const uint32_t aBase = sA + (uint32_t)(warp_m * 32) * FC_PITCH + lmOff;
        const uint32_t bBase = sB + (uint32_t)(warp_n * 64) * FC_PITCH + lmOff;

#pragma unroll
        for (int k16 = 0; k16 < 4; k16++) {
            uint32_t a[2][4];
            ldm4(a[0], aBase + k16 * 32);
            ldm4(a[1], aBase + 16 * FC_PITCH + k16 * 32);
            uint32_t b[4][4];
#pragma unroll
            for (int nb = 0; nb < 4; nb++)
                ldm4(b[nb], bBase + nb * 16 * FC_PITCH + k16 * 32);
#pragma unroll
            for (int mi = 0; mi < 2; mi++)
#pragma unroll
                for (int nb = 0; nb < 4; nb++) {
                    mma16816(d[mi][nb * 2],     a[mi], b[nb][0], b[nb][2]);
                    mma16816(d[mi][nb * 2 + 1], a[mi], b[nb][1], b[nb][3]);
                }
        }
        __syncthreads();
    }

    // epilogue
    const int r = lane >> 2, cg = (lane & 3) * 2;
#pragma unroll
    for (int mi = 0; mi < 2; mi++) {
        int rowb = row0 + warp_m * 32 + mi * 16 + r;
#pragma unroll
        for (int j = 0; j < 8; j++) {
            int nb = j >> 1, h = j & 1;
            int col = col0 + warp_n * 64 + nb * 16 + h * 8 + cg;
            if (col < V_) {
                float2 bv = *(const float2*)(bias + col);
                float2 o0 = { d[mi][j][0] + bv.x, d[mi][j][1] + bv.y };
                float2 o1 = { d[mi][j][2] + bv.x, d[mi][j][3] + bv.y };
                *(float2*)(out + (size_t)rowb * V_ + col) = o0;
                *(float2*)(out + (size_t)(rowb + 8) * V_ + col) = o1;
            }
        }
    }
}

// ---------------- 128x128x8 SGEMM, f32x2 inner ----------------
__global__ __launch_bounds__(256, 2)
void sgemm128(const float* __restrict__ A, const float* __restrict__ B,
              const float* __restrict__ bias, float* __restrict__ C,
              int M, int N, int K) {
    __shared__ float As[8][128];
    __shared__ float Bs[8][128];
    const int tid = threadIdx.x;
    const int row0 = blockIdx.y * 128, col0 = blockIdx.x * 128;
    const int tr = tid >> 4, tc = tid & 15;
    const int aRow = tid >> 1, aCol = (tid & 1) << 2;
    const int bRow = tid >> 5, bCol = (tid & 31) << 2;

    u64 acc[8][4];
#pragma unroll
    for (int i = 0; i < 8; i++)
#pragma unroll
        for (int j = 0; j < 4; j++) acc[i][j] = 0ULL;

    const bool mOK = (row0 + aRow) < M;
    const int bc = col0 + bCol;

    float4 av = make_float4(0, 0, 0, 0), bv = make_float4(0, 0, 0, 0);
    if (mOK) av = *reinterpret_cast<const float4*>(A + (size_t)(row0 + aRow) * K + aCol);
    {
        const float* Bp = B + (size_t)bRow * N + bc;
        if (bc + 3 < N) bv = *reinterpret_cast<const float4*>(Bp);
        else if (bc < N) { bv.x = Bp[0]; if (bc + 1 < N) bv.y = Bp[1]; if (bc + 2 < N) bv.z = Bp[2]; }
    }

    for (int k0 = 0; k0 < K; k0 += 8) {
        As[aCol + 0][aRow] = av.x; As[aCol + 1][aRow] = av.y;
        As[aCol + 2][aRow] = av.z; As[aCol + 3][aRow] = av.w;
        *reinterpret_cast<float4*>(&Bs[bRow][bCol]) = bv;
        __syncthreads();

        if (k0 + 8 < K) {
            av = make_float4(0, 0, 0, 0); bv = make_float4(0, 0, 0, 0);
            if (mOK) av = *reinterpret_cast<const float4*>(A + (size_t)(row0 + aRow) * K + k0 + 8 + aCol);
            const float* Bp = B + (size_t)(k0 + 8 + bRow) * N + bc;
            if (bc + 3 < N) bv = *reinterpret_cast<const float4*>(Bp);
            else if (bc < N) { bv.x = Bp[0]; if (bc + 1 < N) bv.y = Bp[1]; if (bc + 2 < N) bv.z = Bp[2]; }
        }

#pragma unroll
        for (int kk = 0; kk < 8; kk++) {
            float4 a0 = *reinterpret_cast<const float4*>(&As[kk][tr * 8]);
            float4 a1 = *reinterpret_cast<const float4*>(&As[kk][tr * 8 + 4]);
            F4U b0, b1;
            b0.v = *reinterpret_cast<const float4*>(&Bs[kk][tc * 8]);
            b1.v = *reinterpret_cast<const float4*>(&Bs[kk][tc * 8 + 4]);
            float ar[8] = {a0.x, a0.y, a0.z, a0.w, a1.x, a1.y, a1.z, a1.w};
            u64 bb[4] = {b0.u[0], b0.u[1], b1.u[0], b1.u[1]};
#pragma unroll
            for (int i = 0; i < 8; i++) {
                u64 a2 = pack_dup(ar[i]);
#pragma unroll
                for (int j = 0; j < 4; j++) ffma2(acc[i][j], a2, bb[j]);
            }
        }
        __syncthreads();
    }

#pragma unroll
    for (int i = 0; i < 8; i++) {
        int r = row0 + tr * 8 + i;
        if (r >= M) continue;
#pragma unroll
        for (int j = 0; j < 4; j++) {
            float2 v = unpack2(acc[i][j]);
            int c = col0 + tc * 8 + j * 2;
            if (c < N)     C[(size_t)r * N + c]     = v.x + bias[c];
            if (c + 1 < N) C[(size_t)r * N + c + 1] = v.y + bias[c + 1];
        }
    }
}

// ---------------- M=64 k-split GEMM ----------------
__global__ __launch_bounds__(256, 2)
void gemm64_ksplit(const float* __restrict__ X, int ldx,
                   const float* __restrict__ W,
                   float* __restrict__ partial, int N, int Kper) {
    __shared__ float Xs[64][68];
    __shared__ float Ws[64][64];
    const int nc = blockIdx.x, ks = blockIdx.y;
    const int col0 = nc * 64;
    const int kbase = ks * Kper;
    const int tid = threadIdx.x;
    const int tr = tid >> 4, tc = tid & 15;

    u64 acc[4][2];
#pragma unroll
    for (int i = 0; i < 4; i++) { acc[i][0] = 0ULL; acc[i][1] = 0ULL; }

    for (int kt = 0; kt < Kper; kt += 64) {
#pragma unroll
        for (int i = 0; i < 4; i++) {
            int g = tid + 256 * i;
            int r = g >> 4, c4 = (g & 15) << 2;
            float4 xv = *reinterpret_cast<const float4*>(X + (size_t)r * ldx + kbase + kt + c4);
            Xs[r][c4 + 0] = xv.x; Xs[r][c4 + 1] = xv.y; Xs[r][c4 + 2] = xv.z; Xs[r][c4 + 3] = xv.w;
            float4 wv = *reinterpret_cast<const float4*>(W + (size_t)(kbase + kt + r) * N + col0 + c4);
            *reinterpret_cast<float4*>(&Ws[r][c4]) = wv;
        }
        __syncthreads();
#pragma unroll 8
        for (int kk = 0; kk < 64; kk++) {
            u64 d0 = pack_dup(Xs[tr * 4 + 0][kk]);
            u64 d1 = pack_dup(Xs[tr * 4 + 1][kk]);
            u64 d2 = pack_dup(Xs[tr * 4 + 2][kk]);
            u64 d3 = pack_dup(Xs[tr * 4 + 3][kk]);
            const u64* wp = reinterpret_cast<const u64*>(&Ws[kk][tc * 4]);
            u64 b0 = wp[0], b1 = wp[1];
            ffma2(acc[0][0], d0, b0); ffma2(acc[0][1], d0, b1);
            ffma2(acc[1][0], d1, b0); ffma2(acc[1][1], d1, b1);
            ffma2(acc[2][0], d2, b0); ffma2(acc[2][1], d2, b1);
            ffma2(acc[3][0], d3, b0); ffma2(acc[3][1], d3, b1);
        }
        __syncthreads();
    }
#pragma unroll
    for (int i = 0; i < 4; i++) {
        int m = tr * 4 + i;
#pragma unroll
        for (int j = 0; j < 2; j++) {
            float2 v = unpack2(acc[i][j]);
            int c = col0 + tc * 4 + j * 2;
            partial[((size_t)ks * 64 + m) * N + c]     = v.x;
            partial[((size_t)ks * 64 + m) * N + c + 1] = v.y;
        }
    }
}

// ---------------- fused attention ----------------
__global__ __launch_bounds__(256)
void attention_kernel(const float* __restrict__ b_dec, const float* __restrict__ W_full,
                      const float* __restrict__ b_full) {
    const int b = blockIdx.x;
    const int tid = threadIdx.x;
    const int warp = tid >> 5, lane = tid & 31;
    __shared__ float dec_s[512];
    __shared__ float wf_s[512];
    __shared__ float att_s[256];
    __shared__ float red_s[8];

    for (int a = tid; a < 512; a += 256) {
        float s = b_dec[a];
#pragma unroll
        for (int ks = 0; ks < 8; ks++) s += g_decP[((size_t)ks * 64 + b) * 512 + a];
        dec_s[a] = s;
        wf_s[a] = W_full[a];
    }
    __syncthreads();

    for (int p = warp; p < P_; p += 8) {
        const float* ea = g_enc_att + ((size_t)b * P_ + p) * 512;
        float partial = 0.f;
#pragma unroll 4
        for (int a = lane; a < 512; a += 32)
            partial += fmaxf(ea[a] + dec_s[a], 0.f) * wf_s[a];
#pragma unroll
        for (int o = 16; o > 0; o >>= 1) partial += __shfl_xor_sync(0xffffffffu, partial, o);
        if (lane == 0) att_s[p] = partial + b_full[0];
    }
    __syncthreads();

    float v = (tid < P_) ? att_s[tid] : -3.4e38f;
    float m = v;
#pragma unroll
    for (int o = 16; o > 0; o >>= 1) m = fmaxf(m, __shfl_xor_sync(0xffffffffu, m, o));
    if (lane == 0) red_s[warp] = m;
    __syncthreads();
    if (warp == 0) {
        float mm = red_s[lane & 7];
#pragma unroll
        for (int o = 4; o > 0; o >>= 1) mm = fmaxf(mm, __shfl_xor_sync(0xffffffffu, mm, o));
        if (lane == 0) red_s[0] = mm;
    }
    __syncthreads();
    float gmax = red_s[0];
    float e = (tid < P_) ? expf(v - gmax) : 0.f;
    float s = e;
#pragma unroll
    for (int o = 16; o > 0; o >>= 1) s += __shfl_xor_sync(0xffffffffu, s, o);
    __syncthreads();
    if (lane == 0) red_s[warp] = s;
    __syncthreads();
    if (warp == 0) {
        float ss = red_s[lane & 7];
#pragma unroll
        for (int o = 4; o > 0; o >>= 1) ss += __shfl_xor_sync(0xffffffffu, ss, o);
        if (lane == 0) red_s[0] = ss;
    }
    __syncthreads();
    float inv = 1.f / red_s[0];
    if (tid < P_) att_s[tid] = e * inv;
    __syncthreads();

    {
        const float* fb = g_featsT + (size_t)b * P_ * C_ + tid;
        float ctx = 0.f;
#pragma unroll 4
        for (int p = 0; p < P_; p++)
            ctx += fb[(size_t)p * C_] * att_s[p];
        g_X[(size_t)b * 768 + tid] = ctx;
    }
}

// ---------------- LSTM pointwise finalize ----------------
__global__ __launch_bounds__(512)
void lstm_finalize(int t) {
    const int b = blockIdx.x, d = threadIdx.x;
    const size_t pr = ((size_t)b * T_ + t) * 2048;

    float gi = g_pre_gates[pr + d];
    float gf = g_pre_gates[pr + 512 + d];
    float gg = g_pre_gates[pr + 1024 + d];
    float go = g_pre_gates[pr + 1536 + d];
#pragma unroll
    for (int ks = 0; ks < 4; ks++) {
        const float* gp = g_gateP + ((size_t)ks * 64 + b) * 2048;
        gi += gp[d]; gf += gp[512 + d]; gg += gp[1024 + d]; go += gp[1536 + d];
    }
    float si = 1.f / (1.f + expf(-gi));
    float sf = 1.f / (1.f + expf(-gf));
    float so = 1.f / (1.f + expf(-go));
    float tg = tanhf(gg);
    float cn = sf * g_c[(size_t)b * 512 + d] + si * tg;
    float hn = so * tanhf(cn);
    g_c[(size_t)b * 512 + d] = cn;
    g_X[(size_t)b * 768 + 256 + d] = hn;
    g_Hall[((size_t)b * T_ + t) * 512 + d] = hn;
}

// ---------------- launch ----------------
extern "C" void kernel_launch(void* const* d_in, const int* in_sizes, int n_in,
                              void* d_out, int out_size) {
    const float* encF   = (const float*)d_in[0];
    const void*  cap    = d_in[1];
    const float* W_enc  = (const float*)d_in[2];
    const float* b_enc  = (const float*)d_in[3];
    const float* W_dec  = (const float*)d_in[4];
    const float* b_dec  = (const float*)d_in[5];
    const float* W_full = (const float*)d_in[6];
    const float* b_full = (const float*)d_in[7];
    const float* emb    = (const float*)d_in[8];
    const float* W_ih   = (const float*)d_in[9];
    const float* b_ih   = (const float*)d_in[10];
    const float* W_hh   = (const float*)d_in[11];
    const float* b_hh   = (const float*)d_in[12];
    const float* W_fc   = (const float*)d_in[13];
    const float* b_fc   = (const float*)d_in[14];
    float* out = (float*)d_out;

    float *g_featsT_p, *g_enc_att_p, *g_embsG_p, *g_pre_p, *g_WtihE_p, *g_Wbig_p;
    float *g_bias_p, *g_X_p;
    cudaGetSymbolAddress((void**)&g_featsT_p, g_featsT);
    cudaGetSymbolAddress((void**)&g_enc_att_p, g_enc_att);
    cudaGetSymbolAddress((void**)&g_embsG_p, g_embsG);
    cudaGetSymbolAddress((void**)&g_pre_p, g_pre_gates);
    cudaGetSymbolAddress((void**)&g_WtihE_p, g_WtihE);
    cudaGetSymbolAddress((void**)&g_Wbig_p, g_Wbig);
    cudaGetSymbolAddress((void**)&g_bias_p, g_bias_g);
    cudaGetSymbolAddress((void**)&g_X_p, g_X);
    float *g_decP_p, *g_gateP_p;
    cudaGetSymbolAddress((void**)&g_decP_p, g_decP);
    cudaGetSymbolAddress((void**)&g_gateP_p, g_gateP);
    __nv_bfloat16 *g_Ap_p, *g_Bp_p;
    cudaGetSymbolAddress((void**)&g_Ap_p, g_Ap);
    cudaGetSymbolAddress((void**)&g_Bp_p, g_Bp);

    cudaFuncSetAttribute(fc_hmma, cudaFuncAttributeMaxDynamicSharedMemorySize, FC_SMEM);

    // ---- setup (ordered so launch #6 = sgemm128 enc_att for ncu -s 5 -c 1) ----
    detect_dtype<<<1, 256>>>(cap);                                              // 1
    feats_transpose<<<dim3(7, 8, 64), dim3(32, 8)>>>(encF);                     // 2
    transposeW<<<dim3(64, 16), dim3(32, 8)>>>(W_ih, g_WtihE_p, 2048, 768, 0);   // 3
    transposeW<<<dim3(64, 8),  dim3(32, 8)>>>(W_ih, g_Wbig_p, 2048, 768, 512);  // 4
    transposeW<<<dim3(64, 16), dim3(32, 8)>>>(W_hh, g_Wbig_p + (size_t)256 * 2048, 2048, 512, 0); // 5
    sgemm128<<<dim3(4, 98), 256>>>(g_featsT_p, W_enc, b_enc, g_enc_att_p, 12544, 512, 256);       // 6 <- profiled
    gather_emb<<<1280, 128>>>(cap, emb);                                        // 7
    init_state<<<1024, 256>>>();                                                // 8
    make_gate_bias<<<8, 256>>>(b_ih, b_hh);                                     // 9
    build_Bp<<<dim3(938, 16), dim3(32, 8)>>>(W_fc);                             // 10
    pad_Bp<<<208, 256>>>();                                                     // 11
    sgemm128<<<dim3(16, 10), 256>>>(g_embsG_p, g_WtihE_p, g_bias_p, g_pre_p, 1280, 2048, 512);    // 12

    // ---- recurrence ----
    for (int t = 0; t < T_; t++) {
        attention_kernel<<<64, 256>>>(b_dec, W_full, b_full);
        gemm64_ksplit<<<dim3(32, 4), 256>>>(g_X_p, 768, g_Wbig_p, g_gateP_p, 2048, 192);
        lstm_finalize<<<64, 512>>>(t);
        gemm64_ksplit<<<dim3(8, 8), 256>>>(g_X_p + 256, 768, W_dec, g_decP_p, 512, 64);
    }

    // ---- deferred output projection on tensor cores (mma.sync) ----
    build_Ap<<<1280, 256>>>();
    fc_hmma<<<dim3(FC_NPAD / FC_BN, 10), 256, FC_SMEM>>>(g_Ap_p, g_Bp_p, b_fc, out);
}